// round 12
// baseline (speedup 1.0000x reference)
#include <cuda_runtime.h>

// ============================================================================
// MH2SD: attention branch is algebraically dead (softmax over size-1 axis = 1;
// attn rows sum to 1), so out = 1 + gelu(bn(grouped 3x3 conv(x4, local_w))).
//
// R11: 128 threads/CTA @ 3 CTAs/SM -> 128-reg budget (the R8 2-och tile
// retried WITH register headroom). Tile 2 och x 6 col x 2 rows = 12 f32x2
// accs; weights [ci][op][9 tap-pairs] loaded as 4xLDS.128+LDS.64, prefetched
// one ci ahead; all main-loop LDS verified bank-conflict-free. smem = 64KB.
// ============================================================================

#define NPD   24
#define NPIX  576
#define DIMC  128

#define VP_CI        86                    // u64 per ci (3 vrows * 28 used, +2 pad)
#define W_CI         84                    // floats per ci: 4 op * 20 + 4 pad
#define W_OFF_BYTES  44032                 // 64 * 86 * 8
#define RED_STRIDE   9                     // u64 per output (8 partials + pad)
#define W_REGION     21504                 // 64 * 84 * 4  (> 192*9*8 = 13824)
#define SMEM_BYTES   (W_OFF_BYTES + W_REGION)   // 65536

typedef unsigned long long u64;

__device__ __forceinline__ u64 pk(float lo, float hi) {
    u64 r; asm("mov.b64 %0, {%1, %2};" : "=l"(r) : "f"(lo), "f"(hi)); return r;
}
__device__ __forceinline__ void upk(float& lo, float& hi, u64 v) {
    asm("mov.b64 {%0, %1}, %2;" : "=f"(lo), "=f"(hi) : "l"(v));
}
__device__ __forceinline__ void ffma2(u64& d, u64 a, u64 b) {
    asm("fma.rn.f32x2 %0, %1, %2, %0;" : "+l"(d) : "l"(a), "l"(b));
}
__device__ __forceinline__ void fadd2(u64& d, u64 a) {
    asm("add.rn.f32x2 %0, %0, %1;" : "+l"(d) : "l"(a));
}

__global__ void __launch_bounds__(128, 3)
conv_bn_gelu_r11(const float* __restrict__ x,
                 const float* __restrict__ lw,
                 const float* __restrict__ gamma,
                 const float* __restrict__ beta,
                 float* __restrict__ out)
{
    extern __shared__ __align__(16) char smem_raw[];
    u64*   vp  = (u64*)smem_raw;                    // [ci][vrow3][k28] vertical pairs
    float* wsm = (float*)(smem_raw + W_OFF_BYTES);  // [ci][op4][tap9 x och2]
    u64*   red = (u64*)(smem_raw + W_OFF_BYTES);    // reused after main loop

    // CTA: 2 batch x 2 group x 8 och-tiles(8 och) x 12 row-tiles(2 rows)
    const int cta = blockIdx.x;
    const int rt  = cta % 12;
    const int ot  = (cta / 12) & 7;
    const int g   = (cta / 96) & 1;
    const int b   = cta / 192;
    const int tid = threadIdx.x;
    const int r0  = rt * 2;

    // ---- halo zeros: k in {0,1} and {26,27} for every (ci, vrow) ----
    {
        int t2 = tid;                       // 192 tasks over 128 threads
        #pragma unroll
        for (int q = 0; q < 2; q++) {
            if (t2 < 192) {
                int ci = t2 / 3, vr = t2 - ci * 3;
                u64* hz = vp + ci * VP_CI + vr * 28;
                ulonglong2 z; z.x = 0ull; z.y = 0ull;
                ((ulonglong2*)hz)[0]        = z;
                ((ulonglong2*)(hz + 26))[0] = z;
            }
            t2 += 128;
        }
    }

    // ---- input staging: coalesced LDG + shfl vertical pairing ----
    // task T = (ci, m, rr), rr fastest; rr == lane&3, partner = lane+1.
    {
        const float4* x4 = (const float4*)x + b * 18432 + g * 9216;
        #pragma unroll
        for (int q = 0; q < 12; q++) {
            int T   = tid + 128 * q;             // 0..1535
            int ci  = T / 24;
            int rem = T - ci * 24;
            int m   = rem >> 2;                  // 0..5 (float4 within row)
            int rr  = rem & 3;                   // 0..3 (row in window)
            int gr  = r0 - 1 + rr;
            float4 F = make_float4(0.f, 0.f, 0.f, 0.f);
            if ((unsigned)gr < 24u) F = x4[ci * 144 + gr * 6 + m];
            float gx = __shfl_down_sync(0xffffffffu, F.x, 1);
            float gy = __shfl_down_sync(0xffffffffu, F.y, 1);
            float gz = __shfl_down_sync(0xffffffffu, F.z, 1);
            float gw = __shfl_down_sync(0xffffffffu, F.w, 1);
            if (rr < 3) {
                u64* dst = vp + ci * VP_CI + rr * 28 + (m * 4 + 2);
                ulonglong2 t0, t1;
                t0.x = pk(F.x, gx); t0.y = pk(F.y, gy);
                t1.x = pk(F.z, gz); t1.y = pk(F.w, gw);
                ((ulonglong2*)dst)[0]       = t0;
                ((ulonglong2*)(dst + 2))[0] = t1;
            }
        }
    }

    // ---- weight staging: linear coalesced load, scatter to [ci][op][tap2] ----
    {
        const float4* w4 = (const float4*)(lw + (g * 64 + ot * 8) * 576);
        #pragma unroll
        for (int q = 0; q < 9; q++) {
            int i4 = tid + 128 * q;              // 0..1151
            float4 v = w4[i4];
            int i    = i4 * 4;
            int och  = i / 576;
            int r    = i - och * 576;
            int ci   = r / 9;
            int tap  = r - ci * 9;
            int base = (och >> 1) * 20 + (och & 1);
            float vals[4] = {v.x, v.y, v.z, v.w};
            #pragma unroll
            for (int e = 0; e < 4; e++) {
                wsm[ci * W_CI + base + tap * 2] = vals[e];
                tap++;
                if (tap == 9) { tap = 0; ci++; }
            }
        }
    }

    __syncthreads();

    // ---- roles: op(4 och-pairs) x cg(4 col-groups of 6) x split(8, 8 ci) ----
    const int op    = tid & 3;
    const int cg    = (tid >> 2) & 3;
    const int split = tid >> 4;                  // 0..7

    u64 accA[6], accB[6];
    #pragma unroll
    for (int j = 0; j < 6; j++) { accA[j] = 0ull; accB[j] = 0ull; }

    const u64*   vbase = vp  + (split * 8) * VP_CI + cg * 6;
    const float* wbase = wsm + (split * 8) * W_CI + op * 20;

    // prefetch ci=0 weights: 18 floats = 4x LDS.128 + LDS.64
    float4 w0 = *(const float4*)wbase;
    float4 w1 = *(const float4*)(wbase + 4);
    float4 w2 = *(const float4*)(wbase + 8);
    float4 w3 = *(const float4*)(wbase + 12);
    float2 w4v = *(const float2*)(wbase + 16);

    #pragma unroll
    for (int i = 0; i < 8; i++) {
        // current ci's 9 (ochA, ochB) tap pairs
        const float tapsA[9] = {w0.x, w0.z, w1.x, w1.z, w2.x, w2.z, w3.x, w3.z, w4v.x};
        const float tapsB[9] = {w0.y, w0.w, w1.y, w1.w, w2.y, w2.w, w3.y, w3.w, w4v.y};
        if (i < 7) {
            const float* wn = wbase + (i + 1) * W_CI;
            w0 = *(const float4*)wn;
            w1 = *(const float4*)(wn + 4);
            w2 = *(const float4*)(wn + 8);
            w3 = *(const float4*)(wn + 12);
            w4v = *(const float2*)(wn + 16);
        }
        const u64* vc = vbase + i * VP_CI;

        #pragma unroll
        for (int di = 0; di < 3; di++) {
            const ulonglong2* pv = (const ulonglong2*)(vc + di * 28);
            ulonglong2 q0 = pv[0], q1 = pv[1], q2 = pv[2], q3 = pv[3];
            u64 P8 = vc[di * 28 + 8];
            u64 Pt[8];
            Pt[0] = q0.y; Pt[1] = q1.x; Pt[2] = q1.y; Pt[3] = q2.x;
            Pt[4] = q2.y; Pt[5] = q3.x; Pt[6] = q3.y; Pt[7] = P8;

            #pragma unroll
            for (int dj = 0; dj < 3; dj++) {
                float ta = tapsA[di * 3 + dj];
                float tb = tapsB[di * 3 + dj];
                u64 WA = pk(ta, ta);
                u64 WB = pk(tb, tb);
                // same-acc reuse distance = 12 instructions
                ffma2(accA[0], Pt[dj],     WA);
                ffma2(accA[1], Pt[dj + 1], WA);
                ffma2(accA[2], Pt[dj + 2], WA);
                ffma2(accA[3], Pt[dj + 3], WA);
                ffma2(accA[4], Pt[dj + 4], WA);
                ffma2(accA[5], Pt[dj + 5], WA);
                ffma2(accB[0], Pt[dj],     WB);
                ffma2(accB[1], Pt[dj + 1], WB);
                ffma2(accB[2], Pt[dj + 2], WB);
                ffma2(accB[3], Pt[dj + 3], WB);
                ffma2(accB[4], Pt[dj + 4], WB);
                ffma2(accB[5], Pt[dj + 5], WB);
            }
        }
    }

    // ---- split-K reduction (reuse weight region; padded stride 9) ----
    __syncthreads();   // everyone done reading wsm
    {
        const int oA = (op * 2) * 24 + cg * 6;
        const int oB = oA + 24;
        #pragma unroll
        for (int j = 0; j < 6; j++) {
            red[(oA + j) * RED_STRIDE + split] = accA[j];
            red[(oB + j) * RED_STRIDE + split] = accB[j];
        }
    }
    __syncthreads();

    // ---- epilogue: 192 (och, col) vertical pairs over 128 threads ----
    {
        const float inv = rsqrtf(1.0f + 1e-5f);
        const float kI  = 0.70710678118654752440f;
        int t2 = tid;
        #pragma unroll
        for (int q = 0; q < 2; q++) {
            if (t2 < 192) {
                const int och8 = t2 / 24;
                const int col  = t2 - och8 * 24;
                const u64* rb  = red + t2 * RED_STRIDE;
                u64 s0 = rb[0]; fadd2(s0, rb[1]);
                u64 s1 = rb[2]; fadd2(s1, rb[3]);
                u64 s2 = rb[4]; fadd2(s2, rb[5]);
                u64 s3 = rb[6]; fadd2(s3, rb[7]);
                fadd2(s0, s1);
                fadd2(s2, s3);
                fadd2(s0, s2);

                const int   ochg = g * 64 + ot * 8 + och8;
                const float sc   = gamma[ochg] * inv;
                const float bb   = beta[ochg];

                float vt, vb;
                upk(vt, vb, s0);
                float zt = vt * sc + bb;
                float zb = vb * sc + bb;

                float otv = 1.0f + 0.5f * zt * (1.0f + erff(zt * kI));
                float obv = 1.0f + 0.5f * zb * (1.0f + erff(zb * kI));

                float* opt = out + (b * DIMC + ochg) * NPIX + r0 * NPD + col;
                opt[0]   = otv;
                opt[NPD] = obv;
            }
            t2 += 128;
        }
    }
}

extern "C" void kernel_launch(void* const* d_in, const int* in_sizes, int n_in,
                              void* d_out, int out_size) {
    const float* x     = (const float*)d_in[0];   // (2, 576, 128) flat
    const float* lw    = (const float*)d_in[9];   // local_w (128, 64, 3, 3)
    const float* bnc1g = (const float*)d_in[10];  // bnc1_gamma (128)
    const float* bnc1b = (const float*)d_in[11];  // bnc1_beta (128)
    float* out = (float*)d_out;

    cudaFuncSetAttribute(conv_bn_gelu_r11,
                         cudaFuncAttributeMaxDynamicSharedMemorySize,
                         SMEM_BYTES);
    conv_bn_gelu_r11<<<384, 128, SMEM_BYTES>>>(x, lw, bnc1g, bnc1b, out);
}